// round 1
// baseline (speedup 1.0000x reference)
#include <cuda_runtime.h>

#define NPTS    300000
#define NCLS    20
#define KINST   100
#define SCORE_T 0.15f
#define VOTE_T  25
#define NBLK_NMS 148
#define TPB     256

// ---------------- device scratch (static; reset per-launch by k_reset) ------
__device__ float g_sx[NPTS], g_sy[NPTS], g_sz[NPTS];   // shifted = xyz + offset
__device__ int   g_pan[NPTS];                          // semantic argmax
__device__ int   g_inst[NPTS];                         // instance id (fg only)
// compacted candidates (fg && hmap > SCORE_T)
__device__ float g_cx[NPTS], g_cy[NPTS], g_cz[NPTS], g_cs[NPTS];
__device__ int   g_cidx[NPTS];
__device__ int   g_ncand;
// per-round NMS state (slot-per-round: no intra-kernel reset races)
__device__ unsigned long long g_winner[KINST + 1];
__device__ int   g_votes[KINST];
__device__ float g_sumx[KINST], g_sumy[KINST], g_sumz[KINST];
__device__ float g_ctr[KINST * 3];
__device__ int   g_keep[KINST];
__device__ unsigned int g_arrive[KINST];               // software grid barrier slots
__device__ int   g_counts[100 * (KINST + 1)];          // (sem, inst) histogram

// key = (orderable(score) << 32) | (0xFFFFFFFF - orig_index)
// => max key = max score, ties broken toward smallest original index (jnp.argmax)
__device__ __forceinline__ unsigned long long make_key(float s, unsigned idx) {
    return (((unsigned long long)(__float_as_uint(s) ^ 0x80000000u)) << 32)
         | (unsigned long long)(0xFFFFFFFFu - idx);
}

// ---------------- kernel 0: reset all cross-launch state --------------------
__global__ void k_reset() {
    int t = threadIdx.x;
    if (t == 0) g_ncand = 0;
    for (int i = t; i <= KINST; i += blockDim.x) g_winner[i] = 0ull;
    for (int i = t; i < KINST; i += blockDim.x) {
        g_votes[i] = 0; g_sumx[i] = 0.f; g_sumy[i] = 0.f; g_sumz[i] = 0.f;
        g_arrive[i] = 0u;
    }
    for (int i = t; i < 100 * (KINST + 1); i += blockDim.x) g_counts[i] = 0;
}

// ---------------- kernel 1: semantics, shifted coords, candidate compaction -
__global__ void k_init(const float* __restrict__ xyz, const float* __restrict__ sem,
                       const float* __restrict__ off, const float* __restrict__ hmap) {
    int tid = blockIdx.x * blockDim.x + threadIdx.x;
    int stride = gridDim.x * blockDim.x;
    unsigned long long lmax = 0ull;
    for (int i = tid; i < NPTS; i += stride) {
        const float* s = sem + (size_t)i * NCLS;
        float best = s[0]; int bp = 0;
#pragma unroll
        for (int j = 1; j < NCLS; j++) { float v = s[j]; if (v > best) { best = v; bp = j; } }
        g_pan[i] = bp;
        float sx = xyz[i * 3 + 0] + off[i * 3 + 0];
        float sy = xyz[i * 3 + 1] + off[i * 3 + 1];
        float sz = xyz[i * 3 + 2] + off[i * 3 + 2];
        g_sx[i] = sx; g_sy[i] = sy; g_sz[i] = sz;
        float h = hmap[i];
        if (bp >= 1 && bp <= 8 && h > SCORE_T) {
            int pos = atomicAdd(&g_ncand, 1);
            g_cx[pos] = sx; g_cy[pos] = sy; g_cz[pos] = sz;
            g_cs[pos] = h;  g_cidx[pos] = i;
            unsigned long long key = make_key(h, (unsigned)i);
            lmax = lmax > key ? lmax : key;
        }
    }
    // warp-reduce seed for round-0 argmax
    for (int o = 16; o; o >>= 1) {
        unsigned long long v = __shfl_down_sync(0xffffffffu, lmax, o);
        lmax = lmax > v ? lmax : v;
    }
    if ((threadIdx.x & 31) == 0 && lmax) atomicMax(&g_winner[0], lmax);
}

// ---------------- kernel 2: persistent greedy vote-NMS, 1 barrier / round ---
__global__ void __launch_bounds__(TPB) k_nms(float* __restrict__ out) {
    int tid = blockIdx.x * blockDim.x + threadIdx.x;
    int stride = gridDim.x * blockDim.x;
    int nc = g_ncand;
    __shared__ unsigned long long smax[TPB / 32];
    __shared__ float ssx[TPB / 32], ssy[TPB / 32], ssz[TPB / 32];
    __shared__ int   sv[TPB / 32];
    int wid = threadIdx.x >> 5, lane = threadIdx.x & 31;

    for (int k = 0; k < KINST; k++) {
        unsigned long long wkey = __ldcg((const unsigned long long*)&g_winner[k]);
        bool valid = (wkey != 0ull);
        float px = 0.f, py = 0.f, pz = 0.f;
        if (valid) {
            unsigned widx = 0xFFFFFFFFu - (unsigned)(wkey & 0xFFFFFFFFull);
            px = g_sx[widx]; py = g_sy[widx]; pz = g_sz[widx];
        }
        unsigned long long lmax = 0ull;
        float lx = 0.f, ly = 0.f, lz = 0.f; int lv = 0;
        // fused pass: suppress ball of winner[k]  +  argmax for winner[k+1]
        for (int i = tid; i < nc; i += stride) {
            float s = g_cs[i];                 // thread-private ownership (fixed stride)
            if (s > 0.f) {
                float ax = g_cx[i], ay = g_cy[i], az = g_cz[i];
                float dx = ax - px, dy = ay - py, dz = az - pz;
                float d2 = dx * dx + dy * dy + dz * dz;
                if (valid && d2 < 1.0f) {
                    lv++; lx += ax; ly += ay; lz += az;
                    g_cs[i] = -1.f;            // suppress
                } else {
                    unsigned long long kk = make_key(s, (unsigned)g_cidx[i]);
                    lmax = lmax > kk ? lmax : kk;
                }
            }
        }
        // warp reduce
        for (int o = 16; o; o >>= 1) {
            unsigned long long v = __shfl_down_sync(0xffffffffu, lmax, o);
            lmax = lmax > v ? lmax : v;
            lv += __shfl_down_sync(0xffffffffu, lv, o);
            lx += __shfl_down_sync(0xffffffffu, lx, o);
            ly += __shfl_down_sync(0xffffffffu, ly, o);
            lz += __shfl_down_sync(0xffffffffu, lz, o);
        }
        if (lane == 0) { smax[wid] = lmax; sv[wid] = lv; ssx[wid] = lx; ssy[wid] = ly; ssz[wid] = lz; }
        __syncthreads();
        if (threadIdx.x == 0) {
            unsigned long long bm = 0ull; int bv = 0; float bx = 0.f, by = 0.f, bz = 0.f;
            for (int w = 0; w < TPB / 32; w++) {
                bm = bm > smax[w] ? bm : smax[w];
                bv += sv[w]; bx += ssx[w]; by += ssy[w]; bz += ssz[w];
            }
            if (bm) atomicMax(&g_winner[k + 1], bm);
            if (bv) {
                atomicAdd(&g_votes[k], bv);
                atomicAdd(&g_sumx[k], bx); atomicAdd(&g_sumy[k], by); atomicAdd(&g_sumz[k], bz);
            }
            __threadfence();
            atomicAdd(&g_arrive[k], 1u);
            while (*((volatile unsigned int*)&g_arrive[k]) < gridDim.x) { }
            __threadfence();
        }
        __syncthreads();
    }
    // finalize centers / keeps (all rounds complete after barrier 99)
    if (blockIdx.x == 0 && threadIdx.x < KINST) {
        int k = threadIdx.x;
        unsigned long long wkey = __ldcg((const unsigned long long*)&g_winner[k]);
        int   v  = __ldcg((const int*)&g_votes[k]);
        float vx = __ldcg((const float*)&g_sumx[k]);
        float vy = __ldcg((const float*)&g_sumy[k]);
        float vz = __ldcg((const float*)&g_sumz[k]);
        bool kp = (wkey != 0ull) && (v >= VOTE_T);
        float inv = 1.f / fmaxf((float)v, 1.f);
        float cx = kp ? vx * inv : 0.f;
        float cy = kp ? vy * inv : 0.f;
        float cz = kp ? vz * inv : 0.f;
        g_keep[k] = kp ? 1 : 0;
        g_ctr[k * 3 + 0] = cx; g_ctr[k * 3 + 1] = cy; g_ctr[k * 3 + 2] = cz;
        out[k * 3 + 0] = cx; out[k * 3 + 1] = cy; out[k * 3 + 2] = cz;
    }
}

// ---------------- kernel 3: nearest-center assignment + (sem,inst) histogram
__global__ void k_assign(float* __restrict__ out) {
    __shared__ float scx[KINST], scy[KINST], scz[KINST];
    __shared__ int shist[9 * (KINST + 1)];
    for (int t = threadIdx.x; t < KINST; t += blockDim.x) {
        if (g_keep[t]) { scx[t] = g_ctr[t * 3]; scy[t] = g_ctr[t * 3 + 1]; scz[t] = g_ctr[t * 3 + 2]; }
        else           { scx[t] = 1e18f; scy[t] = 1e18f; scz[t] = 1e18f; }  // identical huge d2 -> first index wins
    }
    for (int t = threadIdx.x; t < 9 * (KINST + 1); t += blockDim.x) shist[t] = 0;
    __syncthreads();
    int tid = blockIdx.x * blockDim.x + threadIdx.x;
    int stride = gridDim.x * blockDim.x;
    for (int i = tid; i < NPTS; i += stride) {
        int p = g_pan[i];
        if (p < 1 || p > 8) { out[KINST * 3 + i] = (float)p; continue; }
        float sx = g_sx[i], sy = g_sy[i], sz = g_sz[i];
        int best = 0; float bd = 3.4e38f;
#pragma unroll 4
        for (int k = 0; k < KINST; k++) {
            float dx = sx - scx[k], dy = sy - scy[k], dz = sz - scz[k];
            float d2 = dx * dx + dy * dy + dz * dz;
            if (d2 < bd) { bd = d2; best = k; }     // strict < : first-index tiebreak
        }
        int inst = best + 1;
        g_inst[i] = inst;
        atomicAdd(&shist[p * (KINST + 1) + inst], 1);
    }
    __syncthreads();
    for (int t = threadIdx.x; t < 9 * (KINST + 1); t += blockDim.x) {
        int c = shist[t];
        if (c) atomicAdd(&g_counts[t], c);   // rows 0..8 share the same flat layout
    }
}

// ---------------- kernel 4: per-instance semantic argmax + final gather -----
__global__ void k_final(float* __restrict__ out) {
    __shared__ int ssem[KINST + 1];
    for (int t = threadIdx.x; t <= KINST; t += blockDim.x) {
        int best = g_counts[t]; int bp = 0;        // row 0 is always zero
        for (int p = 1; p <= 8; p++) {             // rows 9..99 are zero, can't beat best>=0
            int c = g_counts[p * (KINST + 1) + t];
            if (c > best) { best = c; bp = p; }
        }
        ssem[t] = bp;
    }
    __syncthreads();
    int tid = blockIdx.x * blockDim.x + threadIdx.x;
    int stride = gridDim.x * blockDim.x;
    for (int i = tid; i < NPTS; i += stride) {
        int p = g_pan[i];
        if (p >= 1 && p <= 8) {
            int inst = g_inst[i];
            out[KINST * 3 + i] = (float)(ssem[inst] + (inst << 16));  // exact: < 2^24
        }
    }
}

extern "C" void kernel_launch(void* const* d_in, const int* in_sizes, int n_in,
                              void* d_out, int out_size) {
    const float* xyz  = (const float*)d_in[0];
    const float* sem  = (const float*)d_in[1];
    const float* off  = (const float*)d_in[2];
    const float* hmap = (const float*)d_in[3];
    float* out = (float*)d_out;
    k_reset <<<1, 256>>>();
    k_init  <<<1184, TPB>>>(xyz, sem, off, hmap);
    k_nms   <<<NBLK_NMS, TPB>>>(out);
    k_assign<<<592, TPB>>>(out);
    k_final <<<592, TPB>>>(out);
}

// round 2
// speedup vs baseline: 1.0743x; 1.0743x over previous
#include <cuda_runtime.h>

#define NPTS    300000
#define NCLS    20
#define KINST   100
#define SCORE_T 0.15f
#define VOTE_T  25
#define TPB     256

// NMS persistent-kernel geometry
#define NB   48                 // blocks (1 per SM, << 148 so always co-resident)
#define NT   512                // threads per block
#define NTHR (NB * NT)          // 24576
#define CPT  5                  // register candidate slots/thread -> cap 122880 (nc ~102k)
#define NWARP (NT / 32)

// ---------------- device scratch ------------------------------------------
__device__ float g_sx[NPTS], g_sy[NPTS], g_sz[NPTS];   // shifted coords
__device__ int   g_pan[NPTS];                          // semantic argmax
__device__ int   g_inst[NPTS];                         // instance id (fg only)
// compacted candidates
__device__ float g_cx[NPTS], g_cy[NPTS], g_cz[NPTS];
__device__ unsigned long long g_ckey[NPTS];
__device__ int   g_ncand;
// centers
__device__ float g_ctr[KINST * 3];
__device__ int   g_keep[KINST];
// per-round barrier + partials (distinct slot per block per round: race-free, no reset needed)
__device__ unsigned int g_arrive[KINST + 1];
__device__ unsigned long long g_pk [(KINST + 1) * NB];
__device__ float g_ppx[(KINST + 1) * NB], g_ppy[(KINST + 1) * NB], g_ppz[(KINST + 1) * NB];
__device__ int   g_pv [(KINST + 1) * NB];
__device__ float g_psx[(KINST + 1) * NB], g_psy[(KINST + 1) * NB], g_psz[(KINST + 1) * NB];
// (sem, inst) histogram
__device__ int   g_counts[100 * (KINST + 1)];

// key = (orderable(score) << 32) | (~orig_index): max key = max score,
// ties broken toward smallest original index (jnp.argmax). Nonzero for all candidates.
__device__ __forceinline__ unsigned long long make_key(float s, unsigned idx) {
    return (((unsigned long long)(__float_as_uint(s) ^ 0x80000000u)) << 32)
         | (unsigned long long)(0xFFFFFFFFu - idx);
}

// ---------------- kernel 0: reset cross-launch state ------------------------
__global__ void k_reset() {
    int t = threadIdx.x;
    if (t == 0) g_ncand = 0;
    for (int i = t; i <= KINST; i += blockDim.x) g_arrive[i] = 0u;
    for (int i = t; i < 100 * (KINST + 1); i += blockDim.x) g_counts[i] = 0;
}

// ---------------- kernel 1: semantics, shifted coords, candidate compaction -
__global__ void k_init(const float* __restrict__ xyz, const float* __restrict__ sem,
                       const float* __restrict__ off, const float* __restrict__ hmap) {
    int tid = blockIdx.x * blockDim.x + threadIdx.x;
    int stride = gridDim.x * blockDim.x;
    for (int i = tid; i < NPTS; i += stride) {
        const float* s = sem + (size_t)i * NCLS;
        float best = s[0]; int bp = 0;
#pragma unroll
        for (int j = 1; j < NCLS; j++) { float v = s[j]; if (v > best) { best = v; bp = j; } }
        g_pan[i] = bp;
        float sx = xyz[i * 3 + 0] + off[i * 3 + 0];
        float sy = xyz[i * 3 + 1] + off[i * 3 + 1];
        float sz = xyz[i * 3 + 2] + off[i * 3 + 2];
        g_sx[i] = sx; g_sy[i] = sy; g_sz[i] = sz;
        float h = hmap[i];
        if (bp >= 1 && bp <= 8 && h > SCORE_T) {
            int pos = atomicAdd(&g_ncand, 1);       // warp-aggregated by ptxas
            g_cx[pos] = sx; g_cy[pos] = sy; g_cz[pos] = sz;
            g_ckey[pos] = make_key(h, (unsigned)i);
        }
    }
}

// ---------------- kernel 2: persistent greedy vote-NMS ----------------------
// Candidates in registers; per round: reg sweep -> block reduce -> distinct-slot
// partial publish -> RED arrive -> leader spin -> warp0 reduces 48 partials
// (key + winner pos + votes + sums) -> broadcast. No same-address atomic trains.
__global__ void __launch_bounds__(NT) k_nms(float* __restrict__ out) {
    int tid = blockIdx.x * NT + threadIdx.x;
    int nc = g_ncand;
    if (nc > NTHR * CPT) nc = NTHR * CPT;           // unreachable safety clamp

    float cx[CPT], cy[CPT], cz[CPT];
    unsigned long long ck[CPT];
#pragma unroll
    for (int j = 0; j < CPT; j++) {
        int i = tid + j * NTHR;
        if (i < nc) { cx[j] = g_cx[i]; cy[j] = g_cy[i]; cz[j] = g_cz[i]; ck[j] = g_ckey[i]; }
        else ck[j] = 0ull;
    }

    __shared__ unsigned long long skey[NWARP];
    __shared__ float smx[NWARP], smy[NWARP], smz[NWARP];
    __shared__ int   sv[NWARP];
    __shared__ float ssx[NWARP], ssy[NWARP], ssz[NWARP];
    __shared__ float bc[3];
    __shared__ unsigned int bvalid;

    int wid = threadIdx.x >> 5, lane = threadIdx.x & 31;
    bool valid = false;                 // winner of previous round
    float px = 0.f, py = 0.f, pz = 0.f;

    for (int k = 0; k <= KINST; k++) {
        // ---- register sweep: suppress+vote ball of winner(k-1), argmax for winner(k)
        unsigned long long lmax = 0ull;
        float mx = 0.f, my = 0.f, mz = 0.f;
        int lv = 0; float lx = 0.f, ly = 0.f, lz = 0.f;
#pragma unroll
        for (int j = 0; j < CPT; j++) {
            unsigned long long key = ck[j];
            if (key) {
                float dx = cx[j] - px, dy = cy[j] - py, dz = cz[j] - pz;
                float d2 = dx * dx + dy * dy + dz * dz;
                if (valid && d2 < 1.0f) {
                    lv++; lx += cx[j]; ly += cy[j]; lz += cz[j];
                    ck[j] = 0ull;
                } else if (key > lmax) {
                    lmax = key; mx = cx[j]; my = cy[j]; mz = cz[j];
                }
            }
        }
        // ---- warp reduce (max-with-pos, sums)
        for (int o = 16; o; o >>= 1) {
            unsigned long long ok = __shfl_down_sync(0xffffffffu, lmax, o);
            float ox = __shfl_down_sync(0xffffffffu, mx, o);
            float oy = __shfl_down_sync(0xffffffffu, my, o);
            float oz = __shfl_down_sync(0xffffffffu, mz, o);
            if (ok > lmax) { lmax = ok; mx = ox; my = oy; mz = oz; }
            lv += __shfl_down_sync(0xffffffffu, lv, o);
            lx += __shfl_down_sync(0xffffffffu, lx, o);
            ly += __shfl_down_sync(0xffffffffu, ly, o);
            lz += __shfl_down_sync(0xffffffffu, lz, o);
        }
        if (lane == 0) { skey[wid] = lmax; smx[wid] = mx; smy[wid] = my; smz[wid] = mz;
                         sv[wid] = lv; ssx[wid] = lx; ssy[wid] = ly; ssz[wid] = lz; }
        __syncthreads();    // (A)

        // ---- leader: block combine, publish partial, arrive, spin
        if (threadIdx.x == 0) {
            unsigned long long bm = 0ull; float bx = 0.f, by = 0.f, bz = 0.f;
            int tv = 0; float tx = 0.f, ty = 0.f, tz = 0.f;
#pragma unroll
            for (int w = 0; w < NWARP; w++) {
                if (skey[w] > bm) { bm = skey[w]; bx = smx[w]; by = smy[w]; bz = smz[w]; }
                tv += sv[w]; tx += ssx[w]; ty += ssy[w]; tz += ssz[w];
            }
            int slot = k * NB + blockIdx.x;
            g_pk[slot] = bm; g_ppx[slot] = bx; g_ppy[slot] = by; g_ppz[slot] = bz;
            g_pv[slot] = tv; g_psx[slot] = tx; g_psy[slot] = ty; g_psz[slot] = tz;
            __threadfence();
            atomicAdd(&g_arrive[k], 1u);            // result unused -> REDG
            while (*(volatile unsigned int*)&g_arrive[k] < NB) { }
            __threadfence();
        }
        __syncwarp();       // warp 0 converges after leader's spin

        // ---- warp 0: reduce the 48 partials (parallel lane loads, one L2 trip)
        if (wid == 0) {
            unsigned long long bm = 0ull; float bx = 0.f, by = 0.f, bz = 0.f;
            int tv = 0; float tx = 0.f, ty = 0.f, tz = 0.f;
            for (int b = lane; b < NB; b += 32) {
                int s = k * NB + b;
                unsigned long long kk = __ldcg(&g_pk[s]);
                float qx = __ldcg(&g_ppx[s]), qy = __ldcg(&g_ppy[s]), qz = __ldcg(&g_ppz[s]);
                int   v  = __ldcg(&g_pv[s]);
                float ax = __ldcg(&g_psx[s]), ay = __ldcg(&g_psy[s]), az = __ldcg(&g_psz[s]);
                if (kk > bm) { bm = kk; bx = qx; by = qy; bz = qz; }
                tv += v; tx += ax; ty += ay; tz += az;
            }
            for (int o = 16; o; o >>= 1) {
                unsigned long long ok = __shfl_down_sync(0xffffffffu, bm, o);
                float ox = __shfl_down_sync(0xffffffffu, bx, o);
                float oy = __shfl_down_sync(0xffffffffu, by, o);
                float oz = __shfl_down_sync(0xffffffffu, bz, o);
                if (ok > bm) { bm = ok; bx = ox; by = oy; bz = oz; }
                tv += __shfl_down_sync(0xffffffffu, tv, o);
                tx += __shfl_down_sync(0xffffffffu, tx, o);
                ty += __shfl_down_sync(0xffffffffu, ty, o);
                tz += __shfl_down_sync(0xffffffffu, tz, o);
            }
            if (lane == 0) {
                if (k >= 1 && blockIdx.x == 0) {     // finalize center k-1
                    bool kp = valid && (tv >= VOTE_T);
                    float inv = 1.f / fmaxf((float)tv, 1.f);
                    float ccx = kp ? tx * inv : 0.f;
                    float ccy = kp ? ty * inv : 0.f;
                    float ccz = kp ? tz * inv : 0.f;
                    g_keep[k - 1] = kp ? 1 : 0;
                    g_ctr[(k - 1) * 3 + 0] = ccx; g_ctr[(k - 1) * 3 + 1] = ccy; g_ctr[(k - 1) * 3 + 2] = ccz;
                    out[(k - 1) * 3 + 0] = ccx; out[(k - 1) * 3 + 1] = ccy; out[(k - 1) * 3 + 2] = ccz;
                }
                bvalid = (bm != 0ull) ? 1u : 0u;
                bc[0] = bx; bc[1] = by; bc[2] = bz;
            }
        }
        __syncthreads();    // (B)
        valid = (bvalid != 0u);
        px = bc[0]; py = bc[1]; pz = bc[2];
        // next write to bc happens only after next round's sync (A) -> no race
    }
}

// ---------------- kernel 3: nearest-center assignment + (sem,inst) histogram
__global__ void k_assign(float* __restrict__ out) {
    __shared__ float scx[KINST], scy[KINST], scz[KINST];
    __shared__ int shist[9 * (KINST + 1)];
    for (int t = threadIdx.x; t < KINST; t += blockDim.x) {
        if (g_keep[t]) { scx[t] = g_ctr[t * 3]; scy[t] = g_ctr[t * 3 + 1]; scz[t] = g_ctr[t * 3 + 2]; }
        else           { scx[t] = 1e18f; scy[t] = 1e18f; scz[t] = 1e18f; }
    }
    for (int t = threadIdx.x; t < 9 * (KINST + 1); t += blockDim.x) shist[t] = 0;
    __syncthreads();
    int tid = blockIdx.x * blockDim.x + threadIdx.x;
    int stride = gridDim.x * blockDim.x;
    for (int i = tid; i < NPTS; i += stride) {
        int p = g_pan[i];
        if (p < 1 || p > 8) { out[KINST * 3 + i] = (float)p; continue; }
        float sx = g_sx[i], sy = g_sy[i], sz = g_sz[i];
        int best = 0; float bd = 3.4e38f;
#pragma unroll 4
        for (int k = 0; k < KINST; k++) {
            float dx = sx - scx[k], dy = sy - scy[k], dz = sz - scz[k];
            float d2 = dx * dx + dy * dy + dz * dz;
            if (d2 < bd) { bd = d2; best = k; }     // strict < : first-index tiebreak
        }
        int inst = best + 1;
        g_inst[i] = inst;
        atomicAdd(&shist[p * (KINST + 1) + inst], 1);
    }
    __syncthreads();
    for (int t = threadIdx.x; t < 9 * (KINST + 1); t += blockDim.x) {
        int c = shist[t];
        if (c) atomicAdd(&g_counts[t], c);
    }
}

// ---------------- kernel 4: per-instance semantic argmax + final gather -----
__global__ void k_final(float* __restrict__ out) {
    __shared__ int ssem[KINST + 1];
    for (int t = threadIdx.x; t <= KINST; t += blockDim.x) {
        int best = g_counts[t]; int bp = 0;
        for (int p = 1; p <= 8; p++) {
            int c = g_counts[p * (KINST + 1) + t];
            if (c > best) { best = c; bp = p; }
        }
        ssem[t] = bp;
    }
    __syncthreads();
    int tid = blockIdx.x * blockDim.x + threadIdx.x;
    int stride = gridDim.x * blockDim.x;
    for (int i = tid; i < NPTS; i += stride) {
        int p = g_pan[i];
        if (p >= 1 && p <= 8) {
            int inst = g_inst[i];
            out[KINST * 3 + i] = (float)(ssem[inst] + (inst << 16));  // exact: < 2^24
        }
    }
}

extern "C" void kernel_launch(void* const* d_in, const int* in_sizes, int n_in,
                              void* d_out, int out_size) {
    const float* xyz  = (const float*)d_in[0];
    const float* sem  = (const float*)d_in[1];
    const float* off  = (const float*)d_in[2];
    const float* hmap = (const float*)d_in[3];
    float* out = (float*)d_out;
    k_reset <<<1, 256>>>();
    k_init  <<<1184, TPB>>>(xyz, sem, off, hmap);
    k_nms   <<<NB, NT>>>(out);
    k_assign<<<1184, TPB>>>(out);
    k_final <<<1184, TPB>>>(out);
}